// round 10
// baseline (speedup 1.0000x reference)
#include <cuda_runtime.h>
#include <math.h>
#include <stdint.h>

#define NTOK 65536
#define DIM  1024
#define BO   64
#define KP   32

// output layout (float32, outputs concatenated in reference tuple order)
#define OFF_EMB 0
#define OFF_ASN 67108864
#define OFF_LOG 69206016
#define OFF_HRD 71303168
#define OFF_Q   71368704
#define OFF_SFT 75563008
#define OFF_ECS 77660160
#define OFF_EDW 77660192
#define OFF_PAT 77662240
#define OFF_USG 77664288

// -------- device scratch (no allocs allowed) --------
__device__ float g_h[NTOK * BO];        // bottleneck pre-LN, 16MB
__device__ float g_Q[NTOK * KP];        // sinkhorn matrix (materialized), 8MB
__device__ float g_Kn[KP * BO];
__device__ float g_dec[KP * DIM];       // decoded patterns (post-LN)
__device__ int   g_hard[NTOK];
__device__ float g_S[3][KP];
__device__ float g_bcs[KP];
__device__ float g_bdw[KP * BO];

// -------- helpers --------
__device__ __forceinline__ float wsum(float v) {
    #pragma unroll
    for (int o = 16; o; o >>= 1) v += __shfl_xor_sync(0xffffffffu, v, o);
    return v;
}

// threefry-2x32, key = (0, 42)  (jax.random.key(42))
__device__ __forceinline__ void threefry42(uint32_t x0, uint32_t x1,
                                           uint32_t& o0, uint32_t& o1) {
    const uint32_t k0 = 0u, k1 = 42u, k2 = 0x1BD11BDAu ^ 42u;
#define TF_R(r) { x0 += x1; x1 = (x1 << (r)) | (x1 >> (32 - (r))); x1 ^= x0; }
    x0 += k0; x1 += k1;
    TF_R(13) TF_R(15) TF_R(26) TF_R(6)   x0 += k1; x1 += k2 + 1u;
    TF_R(17) TF_R(29) TF_R(16) TF_R(24)  x0 += k2; x1 += k0 + 2u;
    TF_R(13) TF_R(15) TF_R(26) TF_R(6)   x0 += k0; x1 += k1 + 3u;
    TF_R(17) TF_R(29) TF_R(16) TF_R(24)  x0 += k1; x1 += k2 + 4u;
    TF_R(13) TF_R(15) TF_R(26) TF_R(6)   x0 += k2; x1 += k0 + 5u;
#undef TF_R
    o0 = x0; o1 = x1;
}

// XLA ErfInv32 (Giles polynomial)
__device__ __forceinline__ float xla_erfinv(float x) {
    float w = -log1pf(-x * x);
    float p;
    if (w < 5.0f) {
        w -= 2.5f;
        p = 2.81022636e-08f;
        p = fmaf(p, w, 3.43273939e-07f);
        p = fmaf(p, w, -3.5233877e-06f);
        p = fmaf(p, w, -4.39150654e-06f);
        p = fmaf(p, w, 0.00021858087f);
        p = fmaf(p, w, -0.00125372503f);
        p = fmaf(p, w, -0.00417768164f);
        p = fmaf(p, w, 0.246640727f);
        p = fmaf(p, w, 1.50140941f);
    } else {
        w = sqrtf(w) - 3.0f;
        p = -0.000200214257f;
        p = fmaf(p, w, 0.000100950558f);
        p = fmaf(p, w, 0.00134934322f);
        p = fmaf(p, w, -0.00367342844f);
        p = fmaf(p, w, 0.00573950773f);
        p = fmaf(p, w, -0.0076224613f);
        p = fmaf(p, w, 0.00943887047f);
        p = fmaf(p, w, 1.00167406f);
        p = fmaf(p, w, 2.83297682f);
    }
    return p * x;
}

// jax partitionable-threefry noise for flat element e of the (B,T,K) array
__device__ __forceinline__ float jax_noise(uint32_t e) {
    uint32_t o0, o1;
    threefry42(0u, e, o0, o1);
    uint32_t bits = o0 ^ o1;
    const float lo = -0.99999994039535522461f;          // nextafter(-1,0)
    float f = __uint_as_float((bits >> 9) | 0x3F800000u) - 1.0f;
    float u = fmaxf(lo, f * 2.0f + lo);
    float nrm = 1.41421356237f * xla_erfinv(u);
    return 0.03f * nrm;
}

// -------- kernels --------
__global__ void k_zero() {
    int tid = threadIdx.x;
    for (int e = tid; e < KP * BO; e += 256) g_bdw[e] = 0.f;
    if (tid < KP) {
        g_bcs[tid] = 0.f;
        g_S[0][tid] = 0.f; g_S[1][tid] = 0.f; g_S[2][tid] = 0.f;
    }
}

// blocks 0..31: decoded[k] = LN(patterns[k] @ W2 + b2, g2, beta2); block 32: Kn = l2norm(patterns)
__global__ void __launch_bounds__(256) k_setup(const float* __restrict__ pat,
                                               const float* __restrict__ W2,
                                               const float* __restrict__ b2,
                                               const float* __restrict__ g2,
                                               const float* __restrict__ beta2) {
    int tid = threadIdx.x;
    if (blockIdx.x < 32) {
        int k = blockIdx.x;
        __shared__ float p[64];
        __shared__ float red[256];
        if (tid < 64) p[tid] = pat[k * 64 + tid];
        __syncthreads();
        float acc[4];
        #pragma unroll
        for (int r = 0; r < 4; r++) acc[r] = b2[r * 256 + tid];
        for (int j = 0; j < 64; j++) {
            float pj = p[j];
            const float* wrow = &W2[j * 1024];
            #pragma unroll
            for (int r = 0; r < 4; r++) acc[r] += pj * wrow[r * 256 + tid];
        }
        float s = acc[0] + acc[1] + acc[2] + acc[3];
        red[tid] = s; __syncthreads();
        for (int o = 128; o > 0; o >>= 1) { if (tid < o) red[tid] += red[tid + o]; __syncthreads(); }
        float mu = red[0] * (1.f / 1024.f);
        __syncthreads();
        float vs = 0.f;
        #pragma unroll
        for (int r = 0; r < 4; r++) { float d = acc[r] - mu; vs += d * d; }
        red[tid] = vs; __syncthreads();
        for (int o = 128; o > 0; o >>= 1) { if (tid < o) red[tid] += red[tid + o]; __syncthreads(); }
        float var = red[0] * (1.f / 1024.f);
        float rstd = rsqrtf(var + 1e-5f);
        #pragma unroll
        for (int r = 0; r < 4; r++) {
            int d = r * 256 + tid;
            g_dec[k * 1024 + d] = (acc[r] - mu) * rstd * g2[d] + beta2[d];
        }
    } else {
        __shared__ float rn[32];
        if (tid < 32) {
            float s = 0.f;
            for (int j = 0; j < 64; j++) { float v = pat[tid * 64 + j]; s += v * v; }
            rn[tid] = 1.0f / fmaxf(sqrtf(s), 1e-12f);
        }
        __syncthreads();
        for (int e = tid; e < KP * BO; e += 256) g_Kn[e] = pat[e] * rn[e >> 6];
    }
}

// h = x @ W1 + b1  (65536x64, K=1024). 128x64 tile / block, fp32 tiled.
__global__ void __launch_bounds__(256) k_gemm1(const float* __restrict__ x,
                                               const float* __restrict__ W1,
                                               const float* __restrict__ b1) {
    __shared__ float xs[32][132];
    __shared__ float ws[32][64];
    int tid = threadIdx.x;
    int tx = tid & 15, ty = tid >> 4;
    int m0 = blockIdx.x * 128;
    float acc[8][4];
    #pragma unroll
    for (int i = 0; i < 8; i++)
        #pragma unroll
        for (int j = 0; j < 4; j++) acc[i][j] = 0.f;

    for (int kt = 0; kt < 1024; kt += 32) {
        #pragma unroll
        for (int r = 0; r < 4; r++) {
            int f = tid + r * 256;
            int row = f >> 3, c4 = f & 7;
            float4 v = *reinterpret_cast<const float4*>(&x[(size_t)(m0 + row) * 1024 + kt + c4 * 4]);
            xs[c4 * 4 + 0][row] = v.x; xs[c4 * 4 + 1][row] = v.y;
            xs[c4 * 4 + 2][row] = v.z; xs[c4 * 4 + 3][row] = v.w;
        }
        #pragma unroll
        for (int r = 0; r < 2; r++) {
            int f = tid + r * 256;
            int row = f >> 4, c4 = f & 15;
            *reinterpret_cast<float4*>(&ws[row][c4 * 4]) =
                *reinterpret_cast<const float4*>(&W1[(size_t)(kt + row) * 64 + c4 * 4]);
        }
        __syncthreads();
        #pragma unroll
        for (int kk = 0; kk < 32; kk++) {
            float4 a0 = *reinterpret_cast<const float4*>(&xs[kk][ty * 8]);
            float4 a1 = *reinterpret_cast<const float4*>(&xs[kk][ty * 8 + 4]);
            float4 bv = *reinterpret_cast<const float4*>(&ws[kk][tx * 4]);
            float av[8] = {a0.x, a0.y, a0.z, a0.w, a1.x, a1.y, a1.z, a1.w};
            float bb[4] = {bv.x, bv.y, bv.z, bv.w};
            #pragma unroll
            for (int i = 0; i < 8; i++)
                #pragma unroll
                for (int j = 0; j < 4; j++) acc[i][j] += av[i] * bb[j];
        }
        __syncthreads();
    }
    float bbias[4];
    #pragma unroll
    for (int j = 0; j < 4; j++) bbias[j] = b1[tx * 4 + j];
    #pragma unroll
    for (int i = 0; i < 8; i++) {
        float4 o;
        o.x = acc[i][0] + bbias[0]; o.y = acc[i][1] + bbias[1];
        o.z = acc[i][2] + bbias[2]; o.w = acc[i][3] + bbias[3];
        *reinterpret_cast<float4*>(&g_h[(size_t)(m0 + ty * 8 + i) * 64 + tx * 4]) = o;
    }
}

// per-token: LN -> Q, l2norm, logits(+noise), softmax, argmax, Q0, accumulators
__global__ void __launch_bounds__(256) k_token(const float* __restrict__ g1v,
                                               const float* __restrict__ b1v,
                                               float* __restrict__ out, float temp) {
    __shared__ float knS[KP][65];
    __shared__ float qs[8][64];
    __shared__ float sB[KP], sW[KP * BO];
    int tid = threadIdx.x, w = tid >> 5, lane = tid & 31;
    for (int e = tid; e < KP * BO; e += 256) { knS[e >> 6][e & 63] = g_Kn[e]; sW[e] = 0.f; }
    if (tid < KP) sB[tid] = 0.f;
    __syncthreads();
    float gg0 = g1v[lane], gg1 = g1v[lane + 32];
    float bb0 = b1v[lane], bb1 = b1v[lane + 32];

    for (int t = 0; t < 8; t++) {
        int n = blockIdx.x * 64 + w * 8 + t;
        float h0 = g_h[(size_t)n * 64 + lane];
        float h1 = g_h[(size_t)n * 64 + 32 + lane];
        float mu = wsum(h0 + h1) * (1.f / 64.f);
        float d0 = h0 - mu, d1 = h1 - mu;
        float var = wsum(d0 * d0 + d1 * d1) * (1.f / 64.f);
        float rstd = rsqrtf(var + 1e-5f);
        float q0 = d0 * rstd * gg0 + bb0;
        float q1 = d1 * rstd * gg1 + bb1;
        out[OFF_Q + (size_t)n * 64 + lane]      = q0;
        out[OFF_Q + (size_t)n * 64 + 32 + lane] = q1;
        float nr = sqrtf(wsum(q0 * q0 + q1 * q1));
        float inv = 1.0f / fmaxf(nr, 1e-12f);
        qs[w][lane] = q0 * inv; qs[w][lane + 32] = q1 * inv;
        __syncwarp();
        float accv = 0.f;
        #pragma unroll
        for (int j = 0; j < 64; j++) accv += qs[w][j] * knS[lane][j];
        float l = accv / temp + jax_noise((uint32_t)n * 32u + (uint32_t)lane);
        out[OFF_LOG + (size_t)n * 32 + lane] = l;
        // argmax (first occurrence on ties)
        float mv = l; int mi = lane;
        #pragma unroll
        for (int o = 16; o; o >>= 1) {
            float v2 = __shfl_xor_sync(0xffffffffu, mv, o);
            int   i2 = __shfl_xor_sync(0xffffffffu, mi, o);
            if (v2 > mv || (v2 == mv && i2 < mi)) { mv = v2; mi = i2; }
        }
        float ev = expf(l - mv);
        float esum = wsum(ev);
        out[OFF_SFT + (size_t)n * 32 + lane] = ev / esum;   // raw softmax (mixed later)
        g_Q[(size_t)n * 32 + lane] = expf((l - mv) / 0.1f) + 1e-8f;
        out[OFF_ASN + (size_t)n * 32 + lane] = (lane == mi) ? 1.0f : 0.0f;
        if (lane == 0) {
            g_hard[n] = mi;
            out[OFF_HRD + n] = (float)mi;
            atomicAdd(&sB[mi], 1.0f);
        }
        atomicAdd(&sW[mi * 64 + lane], q0);
        atomicAdd(&sW[mi * 64 + 32 + lane], q1);
        __syncwarp();
    }
    __syncthreads();
    if (tid < KP) atomicAdd(&g_bcs[tid], sB[tid]);
    for (int e = tid; e < KP * BO; e += 256) atomicAdd(&g_bdw[e], sW[e]);
}

// literal column sum of the materialized g_Q into g_S[s]
// 128 blocks x 256 threads; block b sums tokens [b*512, b*512+512)
__global__ void __launch_bounds__(256) k_colsum(int s) {
    __shared__ float sm[8][32];
    int tid = threadIdx.x, col = tid & 31, grp = tid >> 5;
    int base = blockIdx.x * 512;
    float acc = 0.f;
    for (int t = grp; t < 512; t += 8)
        acc += g_Q[(size_t)(base + t) * 32 + col];
    sm[grp][col] = acc;
    __syncthreads();
    if (grp == 0) {
        float v = sm[0][col];
        #pragma unroll
        for (int g = 1; g < 8; g++) v += sm[g][col];
        atomicAdd(&g_S[s][col], v);
    }
}

// fused col-normalize + row-normalize (one sinkhorn iteration), literal.
// iters 0,1: write Q back. iter 2: write soft mix into out.
__global__ void __launch_bounds__(256) k_cr(int s, int last, float* __restrict__ out) {
    int tid = threadIdx.x, w = tid >> 5, lane = tid & 31;
    float a = 1.0f / fmaxf(g_S[s][lane], 1e-8f);
    for (int t = 0; t < 8; t++) {
        int n = blockIdx.x * 64 + w * 8 + t;
        size_t i = (size_t)n * 32 + lane;
        float q = g_Q[i] * a;              // column normalize
        float rs = wsum(q);
        q = q / fmaxf(rs, 1e-8f);          // row normalize
        if (last) {
            size_t o = OFF_SFT + i;
            out[o] = 0.5f * out[o] + 0.5f * q;
        } else {
            g_Q[i] = q;
        }
    }
}

__global__ void __launch_bounds__(256) k_ema(const float* __restrict__ ecs,
                                             const float* __restrict__ edw,
                                             const float* __restrict__ pu,
                                             float* __restrict__ out) {
    __shared__ float necs[32], csv[32], inorm[32], vbuf[2048], red[2];
    int tid = threadIdx.x;
    if (tid < 32) {
        float v = 0.99f * ecs[tid] + 0.01f * g_bcs[tid];
        necs[tid] = v;
        out[OFF_ECS + tid] = v;
    }
    __syncthreads();
    if (tid == 0) {
        float s = 0.f, bs = 0.f;
        for (int k = 0; k < 32; k++) { s += necs[k]; bs += g_bcs[k]; }
        red[0] = s; red[1] = bs;
    }
    __syncthreads();
    float nsum = red[0], bsum = red[1];
    if (tid < 32) {
        float c = (necs[tid] + 1e-5f) / (nsum + 3.2e-4f) * nsum;
        csv[tid] = fmaxf(c, 1.0f);
        float u = g_bcs[tid] / (bsum + 1e-8f);
        out[OFF_USG + tid] = 0.9f * pu[tid] + 0.1f * u;
    }
    __syncthreads();
    for (int e = tid; e < 2048; e += 256) {
        float nd = 0.99f * edw[e] + 0.01f * g_bdw[e];
        out[OFF_EDW + e] = nd;
        vbuf[e] = nd / csv[e >> 6];
    }
    __syncthreads();
    if (tid < 32) {
        float s = 0.f;
        for (int j = 0; j < 64; j++) { float v = vbuf[tid * 64 + j]; s += v * v; }
        inorm[tid] = 1.0f / fmaxf(sqrtf(s), 1e-12f);
    }
    __syncthreads();
    for (int e = tid; e < 2048; e += 256) out[OFF_PAT + e] = vbuf[e] * inorm[e >> 6];
}

// pattern_emb[n] = decoded[hard[n]]  (float4 gather-scatter, 256MB write)
__global__ void __launch_bounds__(256) k_scatter(float* __restrict__ out) {
    size_t idx = (size_t)blockIdx.x * 256 + threadIdx.x;
    int n = (int)(idx >> 8);
    int j = (int)(idx & 255);
    int hn = g_hard[n];
    const float4* dec4 = reinterpret_cast<const float4*>(g_dec);
    reinterpret_cast<float4*>(out)[idx] = dec4[(size_t)hn * 256 + j];
}

extern "C" void kernel_launch(void* const* d_in, const int* in_sizes, int n_in,
                              void* d_out, int out_size) {
    const float* x     = (const float*)d_in[0];
    const float* W1    = (const float*)d_in[1];
    const float* b1    = (const float*)d_in[2];
    const float* g1    = (const float*)d_in[3];
    const float* beta1 = (const float*)d_in[4];
    const float* pat   = (const float*)d_in[5];
    const float* W2    = (const float*)d_in[6];
    const float* b2    = (const float*)d_in[7];
    const float* g2    = (const float*)d_in[8];
    const float* beta2 = (const float*)d_in[9];
    const float* ecs   = (const float*)d_in[10];
    const float* edw   = (const float*)d_in[11];
    const float* pu    = (const float*)d_in[12];
    float* out = (float*)d_out;

    double prog = (60.0 - 15.0) / 85.0;
    float temp = (float)(0.2 + 0.8 * (1.0 + cos(3.14159265358979323846 * prog)) * 0.5);

    k_zero<<<1, 256>>>();
    k_setup<<<33, 256>>>(pat, W2, b2, g2, beta2);
    k_gemm1<<<512, 256>>>(x, W1, b1);
    k_token<<<1024, 256>>>(g1, beta1, out, temp);
    // literal sinkhorn: 3 x (column sums over materialized Q, then col+row normalize)
    k_colsum<<<128, 256>>>(0);
    k_cr<<<1024, 256>>>(0, 0, out);
    k_colsum<<<128, 256>>>(1);
    k_cr<<<1024, 256>>>(1, 0, out);
    k_colsum<<<128, 256>>>(2);
    k_cr<<<1024, 256>>>(2, 1, out);
    k_ema<<<1, 256>>>(ecs, edw, pu, out);
    k_scatter<<<65536, 256>>>(out);
}

// round 11
// speedup vs baseline: 1.0126x; 1.0126x over previous
#include <cuda_runtime.h>
#include <math.h>
#include <stdint.h>

#define NTOK 65536
#define DIM  1024
#define BO   64
#define KP   32

// output layout (float32, outputs concatenated in reference tuple order)
#define OFF_EMB 0
#define OFF_ASN 67108864
#define OFF_LOG 69206016
#define OFF_HRD 71303168
#define OFF_Q   71368704
#define OFF_SFT 75563008
#define OFF_ECS 77660160
#define OFF_EDW 77660192
#define OFF_PAT 77662240
#define OFF_USG 77664288

// -------- device scratch (no allocs allowed) --------
__device__ float g_h[NTOK * BO];        // bottleneck pre-LN, 16MB
__device__ float g_Q[NTOK * KP];        // sinkhorn matrix (materialized), 8MB
__device__ float g_Kn[KP * BO];
__device__ float g_dec[KP * DIM];       // decoded patterns (post-LN)
__device__ int   g_hard[NTOK];
__device__ float g_S[3][KP];
__device__ float g_bcs[KP];
__device__ float g_bdw[KP * BO];

// -------- helpers --------
__device__ __forceinline__ float wsum(float v) {
    #pragma unroll
    for (int o = 16; o; o >>= 1) v += __shfl_xor_sync(0xffffffffu, v, o);
    return v;
}

// threefry-2x32, key = (0, 42)  (jax.random.key(42))
__device__ __forceinline__ void threefry42(uint32_t x0, uint32_t x1,
                                           uint32_t& o0, uint32_t& o1) {
    const uint32_t k0 = 0u, k1 = 42u, k2 = 0x1BD11BDAu ^ 42u;
#define TF_R(r) { x0 += x1; x1 = (x1 << (r)) | (x1 >> (32 - (r))); x1 ^= x0; }
    x0 += k0; x1 += k1;
    TF_R(13) TF_R(15) TF_R(26) TF_R(6)   x0 += k1; x1 += k2 + 1u;
    TF_R(17) TF_R(29) TF_R(16) TF_R(24)  x0 += k2; x1 += k0 + 2u;
    TF_R(13) TF_R(15) TF_R(26) TF_R(6)   x0 += k0; x1 += k1 + 3u;
    TF_R(17) TF_R(29) TF_R(16) TF_R(24)  x0 += k1; x1 += k2 + 4u;
    TF_R(13) TF_R(15) TF_R(26) TF_R(6)   x0 += k2; x1 += k0 + 5u;
#undef TF_R
    o0 = x0; o1 = x1;
}

// XLA ErfInv32 (Giles polynomial)
__device__ __forceinline__ float xla_erfinv(float x) {
    float w = -log1pf(-x * x);
    float p;
    if (w < 5.0f) {
        w -= 2.5f;
        p = 2.81022636e-08f;
        p = fmaf(p, w, 3.43273939e-07f);
        p = fmaf(p, w, -3.5233877e-06f);
        p = fmaf(p, w, -4.39150654e-06f);
        p = fmaf(p, w, 0.00021858087f);
        p = fmaf(p, w, -0.00125372503f);
        p = fmaf(p, w, -0.00417768164f);
        p = fmaf(p, w, 0.246640727f);
        p = fmaf(p, w, 1.50140941f);
    } else {
        w = sqrtf(w) - 3.0f;
        p = -0.000200214257f;
        p = fmaf(p, w, 0.000100950558f);
        p = fmaf(p, w, 0.00134934322f);
        p = fmaf(p, w, -0.00367342844f);
        p = fmaf(p, w, 0.00573950773f);
        p = fmaf(p, w, -0.0076224613f);
        p = fmaf(p, w, 0.00943887047f);
        p = fmaf(p, w, 1.00167406f);
        p = fmaf(p, w, 2.83297682f);
    }
    return p * x;
}

// jax partitionable-threefry noise for flat element e of the (B,T,K) array
__device__ __forceinline__ float jax_noise(uint32_t e) {
    uint32_t o0, o1;
    threefry42(0u, e, o0, o1);
    uint32_t bits = o0 ^ o1;
    const float lo = -0.99999994039535522461f;          // nextafter(-1,0)
    float f = __uint_as_float((bits >> 9) | 0x3F800000u) - 1.0f;
    float u = fmaxf(lo, f * 2.0f + lo);
    float nrm = 1.41421356237f * xla_erfinv(u);
    return 0.03f * nrm;
}

// -------- kernels --------
__global__ void k_zero() {
    int tid = threadIdx.x;
    for (int e = tid; e < KP * BO; e += 256) g_bdw[e] = 0.f;
    if (tid < KP) {
        g_bcs[tid] = 0.f;
        g_S[0][tid] = 0.f; g_S[1][tid] = 0.f; g_S[2][tid] = 0.f;
    }
}

// blocks 0..31: decoded[k] = LN(patterns[k] @ W2 + b2, g2, beta2); block 32: Kn = l2norm(patterns)
__global__ void __launch_bounds__(256) k_setup(const float* __restrict__ pat,
                                               const float* __restrict__ W2,
                                               const float* __restrict__ b2,
                                               const float* __restrict__ g2,
                                               const float* __restrict__ beta2) {
    int tid = threadIdx.x;
    if (blockIdx.x < 32) {
        int k = blockIdx.x;
        __shared__ float p[64];
        __shared__ float red[256];
        if (tid < 64) p[tid] = pat[k * 64 + tid];
        __syncthreads();
        float acc[4];
        #pragma unroll
        for (int r = 0; r < 4; r++) acc[r] = b2[r * 256 + tid];
        for (int j = 0; j < 64; j++) {
            float pj = p[j];
            const float* wrow = &W2[j * 1024];
            #pragma unroll
            for (int r = 0; r < 4; r++) acc[r] += pj * wrow[r * 256 + tid];
        }
        float s = acc[0] + acc[1] + acc[2] + acc[3];
        red[tid] = s; __syncthreads();
        for (int o = 128; o > 0; o >>= 1) { if (tid < o) red[tid] += red[tid + o]; __syncthreads(); }
        float mu = red[0] * (1.f / 1024.f);
        __syncthreads();
        float vs = 0.f;
        #pragma unroll
        for (int r = 0; r < 4; r++) { float d = acc[r] - mu; vs += d * d; }
        red[tid] = vs; __syncthreads();
        for (int o = 128; o > 0; o >>= 1) { if (tid < o) red[tid] += red[tid + o]; __syncthreads(); }
        float var = red[0] * (1.f / 1024.f);
        float rstd = rsqrtf(var + 1e-5f);
        #pragma unroll
        for (int r = 0; r < 4; r++) {
            int d = r * 256 + tid;
            g_dec[k * 1024 + d] = (acc[r] - mu) * rstd * g2[d] + beta2[d];
        }
    } else {
        __shared__ float rn[32];
        if (tid < 32) {
            float s = 0.f;
            for (int j = 0; j < 64; j++) { float v = pat[tid * 64 + j]; s += v * v; }
            rn[tid] = 1.0f / fmaxf(sqrtf(s), 1e-12f);
        }
        __syncthreads();
        for (int e = tid; e < KP * BO; e += 256) g_Kn[e] = pat[e] * rn[e >> 6];
    }
}

// h = x @ W1 + b1  (65536x64, K=1024). 128x64 tile / block, fp32 tiled.
__global__ void __launch_bounds__(256) k_gemm1(const float* __restrict__ x,
                                               const float* __restrict__ W1,
                                               const float* __restrict__ b1) {
    __shared__ float xs[32][132];
    __shared__ float ws[32][64];
    int tid = threadIdx.x;
    int tx = tid & 15, ty = tid >> 4;
    int m0 = blockIdx.x * 128;
    float acc[8][4];
    #pragma unroll
    for (int i = 0; i < 8; i++)
        #pragma unroll
        for (int j = 0; j < 4; j++) acc[i][j] = 0.f;

    for (int kt = 0; kt < 1024; kt += 32) {
        #pragma unroll
        for (int r = 0; r < 4; r++) {
            int f = tid + r * 256;
            int row = f >> 3, c4 = f & 7;
            float4 v = *reinterpret_cast<const float4*>(&x[(size_t)(m0 + row) * 1024 + kt + c4 * 4]);
            xs[c4 * 4 + 0][row] = v.x; xs[c4 * 4 + 1][row] = v.y;
            xs[c4 * 4 + 2][row] = v.z; xs[c4 * 4 + 3][row] = v.w;
        }
        #pragma unroll
        for (int r = 0; r < 2; r++) {
            int f = tid + r * 256;
            int row = f >> 4, c4 = f & 15;
            *reinterpret_cast<float4*>(&ws[row][c4 * 4]) =
                *reinterpret_cast<const float4*>(&W1[(size_t)(kt + row) * 64 + c4 * 4]);
        }
        __syncthreads();
        #pragma unroll
        for (int kk = 0; kk < 32; kk++) {
            float4 a0 = *reinterpret_cast<const float4*>(&xs[kk][ty * 8]);
            float4 a1 = *reinterpret_cast<const float4*>(&xs[kk][ty * 8 + 4]);
            float4 bv = *reinterpret_cast<const float4*>(&ws[kk][tx * 4]);
            float av[8] = {a0.x, a0.y, a0.z, a0.w, a1.x, a1.y, a1.z, a1.w};
            float bb[4] = {bv.x, bv.y, bv.z, bv.w};
            #pragma unroll
            for (int i = 0; i < 8; i++)
                #pragma unroll
                for (int j = 0; j < 4; j++) acc[i][j] += av[i] * bb[j];
        }
        __syncthreads();
    }
    float bbias[4];
    #pragma unroll
    for (int j = 0; j < 4; j++) bbias[j] = b1[tx * 4 + j];
    #pragma unroll
    for (int i = 0; i < 8; i++) {
        float4 o;
        o.x = acc[i][0] + bbias[0]; o.y = acc[i][1] + bbias[1];
        o.z = acc[i][2] + bbias[2]; o.w = acc[i][3] + bbias[3];
        *reinterpret_cast<float4*>(&g_h[(size_t)(m0 + ty * 8 + i) * 64 + tx * 4]) = o;
    }
}

// per-token: LN -> Q, l2norm, logits(+noise), softmax, argmax, Q0, accumulators
__global__ void __launch_bounds__(256) k_token(const float* __restrict__ g1v,
                                               const float* __restrict__ b1v,
                                               float* __restrict__ out, float temp) {
    __shared__ float knS[KP][65];
    __shared__ float qs[8][64];
    __shared__ float sB[KP], sW[KP * BO];
    int tid = threadIdx.x, w = tid >> 5, lane = tid & 31;
    for (int e = tid; e < KP * BO; e += 256) { knS[e >> 6][e & 63] = g_Kn[e]; sW[e] = 0.f; }
    if (tid < KP) sB[tid] = 0.f;
    __syncthreads();
    float gg0 = g1v[lane], gg1 = g1v[lane + 32];
    float bb0 = b1v[lane], bb1 = b1v[lane + 32];

    for (int t = 0; t < 8; t++) {
        int n = blockIdx.x * 64 + w * 8 + t;
        float h0 = g_h[(size_t)n * 64 + lane];
        float h1 = g_h[(size_t)n * 64 + 32 + lane];
        float mu = wsum(h0 + h1) * (1.f / 64.f);
        float d0 = h0 - mu, d1 = h1 - mu;
        float var = wsum(d0 * d0 + d1 * d1) * (1.f / 64.f);
        float rstd = rsqrtf(var + 1e-5f);
        float q0 = d0 * rstd * gg0 + bb0;
        float q1 = d1 * rstd * gg1 + bb1;
        out[OFF_Q + (size_t)n * 64 + lane]      = q0;
        out[OFF_Q + (size_t)n * 64 + 32 + lane] = q1;
        float nr = sqrtf(wsum(q0 * q0 + q1 * q1));
        float inv = 1.0f / fmaxf(nr, 1e-12f);
        qs[w][lane] = q0 * inv; qs[w][lane + 32] = q1 * inv;
        __syncwarp();
        float accv = 0.f;
        #pragma unroll
        for (int j = 0; j < 64; j++) accv += qs[w][j] * knS[lane][j];
        float l = accv / temp + jax_noise((uint32_t)n * 32u + (uint32_t)lane);
        out[OFF_LOG + (size_t)n * 32 + lane] = l;
        // argmax (first occurrence on ties)
        float mv = l; int mi = lane;
        #pragma unroll
        for (int o = 16; o; o >>= 1) {
            float v2 = __shfl_xor_sync(0xffffffffu, mv, o);
            int   i2 = __shfl_xor_sync(0xffffffffu, mi, o);
            if (v2 > mv || (v2 == mv && i2 < mi)) { mv = v2; mi = i2; }
        }
        float ev = expf(l - mv);
        float esum = wsum(ev);
        out[OFF_SFT + (size_t)n * 32 + lane] = ev / esum;   // raw softmax (mixed later)
        g_Q[(size_t)n * 32 + lane] = expf((l - mv) / 0.1f) + 1e-8f;
        out[OFF_ASN + (size_t)n * 32 + lane] = (lane == mi) ? 1.0f : 0.0f;
        if (lane == 0) {
            g_hard[n] = mi;
            out[OFF_HRD + n] = (float)mi;
            atomicAdd(&sB[mi], 1.0f);
        }
        atomicAdd(&sW[mi * 64 + lane], q0);
        atomicAdd(&sW[mi * 64 + 32 + lane], q1);
        __syncwarp();
    }
    __syncthreads();
    if (tid < KP) atomicAdd(&g_bcs[tid], sB[tid]);
    for (int e = tid; e < KP * BO; e += 256) atomicAdd(&g_bdw[e], sW[e]);
}

// literal column sum of the materialized g_Q into g_S[s]
// 128 blocks x 256 threads; block b sums tokens [b*512, b*512+512)
__global__ void __launch_bounds__(256) k_colsum(int s) {
    __shared__ float sm[8][32];
    int tid = threadIdx.x, col = tid & 31, grp = tid >> 5;
    int base = blockIdx.x * 512;
    float acc = 0.f;
    for (int t = grp; t < 512; t += 8)
        acc += g_Q[(size_t)(base + t) * 32 + col];
    sm[grp][col] = acc;
    __syncthreads();
    if (grp == 0) {
        float v = sm[0][col];
        #pragma unroll
        for (int g = 1; g < 8; g++) v += sm[g][col];
        atomicAdd(&g_S[s][col], v);
    }
}

// fused col-normalize + row-normalize (one sinkhorn iteration), literal.
// iters 0,1: write Q back. iter 2: write soft mix into out.
__global__ void __launch_bounds__(256) k_cr(int s, int last, float* __restrict__ out) {
    int tid = threadIdx.x, w = tid >> 5, lane = tid & 31;
    float a = 1.0f / fmaxf(g_S[s][lane], 1e-8f);
    for (int t = 0; t < 8; t++) {
        int n = blockIdx.x * 64 + w * 8 + t;
        size_t i = (size_t)n * 32 + lane;
        float q = g_Q[i] * a;              // column normalize
        float rs = wsum(q);
        q = q / fmaxf(rs, 1e-8f);          // row normalize
        if (last) {
            size_t o = OFF_SFT + i;
            out[o] = 0.5f * out[o] + 0.5f * q;
        } else {
            g_Q[i] = q;
        }
    }
}

__global__ void __launch_bounds__(256) k_ema(const float* __restrict__ ecs,
                                             const float* __restrict__ edw,
                                             const float* __restrict__ pu,
                                             float* __restrict__ out) {
    __shared__ float necs[32], csv[32], inorm[32], vbuf[2048], red[2];
    int tid = threadIdx.x;
    if (tid < 32) {
        float v = 0.99f * ecs[tid] + 0.01f * g_bcs[tid];
        necs[tid] = v;
        out[OFF_ECS + tid] = v;
    }
    __syncthreads();
    if (tid == 0) {
        float s = 0.f, bs = 0.f;
        for (int k = 0; k < 32; k++) { s += necs[k]; bs += g_bcs[k]; }
        red[0] = s; red[1] = bs;
    }
    __syncthreads();
    float nsum = red[0], bsum = red[1];
    if (tid < 32) {
        float c = (necs[tid] + 1e-5f) / (nsum + 3.2e-4f) * nsum;
        csv[tid] = fmaxf(c, 1.0f);
        float u = g_bcs[tid] / (bsum + 1e-8f);
        out[OFF_USG + tid] = 0.9f * pu[tid] + 0.1f * u;
    }
    __syncthreads();
    for (int e = tid; e < 2048; e += 256) {
        float nd = 0.99f * edw[e] + 0.01f * g_bdw[e];
        out[OFF_EDW + e] = nd;
        vbuf[e] = nd / csv[e >> 6];
    }
    __syncthreads();
    if (tid < 32) {
        float s = 0.f;
        for (int j = 0; j < 64; j++) { float v = vbuf[tid * 64 + j]; s += v * v; }
        inorm[tid] = 1.0f / fmaxf(sqrtf(s), 1e-12f);
    }
    __syncthreads();
    for (int e = tid; e < 2048; e += 256) out[OFF_PAT + e] = vbuf[e] * inorm[e >> 6];
}

// pattern_emb[n] = decoded[hard[n]]  (float4 gather-scatter, 256MB write)
__global__ void __launch_bounds__(256) k_scatter(float* __restrict__ out) {
    size_t idx = (size_t)blockIdx.x * 256 + threadIdx.x;
    int n = (int)(idx >> 8);
    int j = (int)(idx & 255);
    int hn = g_hard[n];
    const float4* dec4 = reinterpret_cast<const float4*>(g_dec);
    reinterpret_cast<float4*>(out)[idx] = dec4[(size_t)hn * 256 + j];
}

extern "C" void kernel_launch(void* const* d_in, const int* in_sizes, int n_in,
                              void* d_out, int out_size) {
    const float* x     = (const float*)d_in[0];
    const float* W1    = (const float*)d_in[1];
    const float* b1    = (const float*)d_in[2];
    const float* g1    = (const float*)d_in[3];
    const float* beta1 = (const float*)d_in[4];
    const float* pat   = (const float*)d_in[5];
    const float* W2    = (const float*)d_in[6];
    const float* b2    = (const float*)d_in[7];
    const float* g2    = (const float*)d_in[8];
    const float* beta2 = (const float*)d_in[9];
    const float* ecs   = (const float*)d_in[10];
    const float* edw   = (const float*)d_in[11];
    const float* pu    = (const float*)d_in[12];
    float* out = (float*)d_out;

    double prog = (60.0 - 15.0) / 85.0;
    float temp = (float)(0.2 + 0.8 * (1.0 + cos(3.14159265358979323846 * prog)) * 0.5);

    k_zero<<<1, 256>>>();
    k_setup<<<33, 256>>>(pat, W2, b2, g2, beta2);
    k_gemm1<<<512, 256>>>(x, W1, b1);
    k_token<<<1024, 256>>>(g1, beta1, out, temp);
    // literal sinkhorn: 3 x (column sums over materialized Q, then col+row normalize)
    k_colsum<<<128, 256>>>(0);
    k_cr<<<1024, 256>>>(0, 0, out);
    k_colsum<<<128, 256>>>(1);
    k_cr<<<1024, 256>>>(1, 0, out);
    k_colsum<<<128, 256>>>(2);
    k_cr<<<1024, 256>>>(2, 1, out);
    k_ema<<<1, 256>>>(ecs, edw, pu, out);
    k_scatter<<<65536, 256>>>(out);
}